// round 15
// baseline (speedup 1.0000x reference)
#include <cuda_runtime.h>
#include <cstdint>

#define NN 50000
#define EE 800000
#define CC 128
#define CAP 64           // bucket capacity (deg~Poisson(16); P(>64)~2e-18/node)

// Scratch (static __device__ arrays — allocation-free).
// g_fill starts zero (static init) and is RESET by gather_kernel after use,
// so every run of the pipeline (correctness, capture, each replay) sees
// zeroed cursors without a dedicated zero kernel.
__device__ float    g_hs[(size_t)NN * CC];       // hs[j] = (x@W)[j] * dinv[j]
__device__ int      g_fill[NN];                  // per-node cursor == in-degree
__device__ uint16_t g_srcidx[(size_t)NN * CAP];  // padded buckets (u16: NN<65536)

// ---------------------------------------------------------------------------
// 1) bucket edges directly (order within bucket irrelevant)
__global__ void fill_kernel(const int* __restrict__ ei) {
    int e = blockIdx.x * blockDim.x + threadIdx.x;
    if (e < EE) {
        int src = ei[e];
        int dst = ei[EE + e];
        int pos = atomicAdd(&g_fill[dst], 1);
        if (pos < CAP)                       // safety guard (never taken)
            g_srcidx[(size_t)dst * CAP + pos] = (uint16_t)src;
    }
}

// ---------------------------------------------------------------------------
// 2) GEMM (fp32 SIMT, at FFMA floor): hs = (x @ W) * dinv[row],
//    dinv inline from fill counters. 256 threads, 64 rows/block;
//    thread = 8 rows x 4 cols. x loaded .cs (read-once).
__global__ void gemm_kernel(const float* __restrict__ x,
                            const float* __restrict__ w) {
    __shared__ float4 sx[64][32];   // 32 KB
    const int row0 = blockIdx.x * 64;
    const int t = threadIdx.x;
    const int lane = t & 31;
    const int wg = t >> 5;          // 8 warps
    const int r0 = wg * 8;

    const float4* x4 = (const float4*)x;
    for (int i = t; i < 64 * 32; i += 256) {
        int r = i >> 5, c = i & 31;
        int row = row0 + r;
        sx[r][c] = (row < NN) ? __ldcs(&x4[(size_t)row * 32 + c])
                              : make_float4(0.f, 0.f, 0.f, 0.f);
    }
    __syncthreads();

    float acc[8][4] = {};
    const float4* w4 = (const float4*)w;

#pragma unroll 2
    for (int k4 = 0; k4 < 32; k4++) {
        float4 wv0 = w4[(k4 * 4 + 0) * 32 + lane];
        float4 wv1 = w4[(k4 * 4 + 1) * 32 + lane];
        float4 wv2 = w4[(k4 * 4 + 2) * 32 + lane];
        float4 wv3 = w4[(k4 * 4 + 3) * 32 + lane];
#pragma unroll
        for (int r = 0; r < 8; r++) {
            float4 xv = sx[r0 + r][k4];  // broadcast, conflict-free
            acc[r][0] += xv.x * wv0.x; acc[r][1] += xv.x * wv0.y;
            acc[r][2] += xv.x * wv0.z; acc[r][3] += xv.x * wv0.w;
            acc[r][0] += xv.y * wv1.x; acc[r][1] += xv.y * wv1.y;
            acc[r][2] += xv.y * wv1.z; acc[r][3] += xv.y * wv1.w;
            acc[r][0] += xv.z * wv2.x; acc[r][1] += xv.z * wv2.y;
            acc[r][2] += xv.z * wv2.z; acc[r][3] += xv.z * wv2.w;
            acc[r][0] += xv.w * wv3.x; acc[r][1] += xv.w * wv3.y;
            acc[r][2] += xv.w * wv3.z; acc[r][3] += xv.w * wv3.w;
        }
    }

    float4* hs4 = (float4*)g_hs;
#pragma unroll
    for (int r = 0; r < 8; r++) {
        int row = row0 + r0 + r;
        if (row < NN) {
            float d = rsqrtf((float)(g_fill[row] + 1));   // dinv inline
            hs4[(size_t)row * 32 + lane] =
                make_float4(acc[r][0] * d, acc[r][1] * d,
                            acc[r][2] * d, acc[r][3] * d);
        }
    }
}

// ---------------------------------------------------------------------------
// 3) Bucket gather (R12-proven): one warp per node; dual accumulators;
//    fused dinv/bias/relu epilogue; streaming store; resets g_fill for the
//    next run.
__global__ void gather_kernel(float* __restrict__ out,
                              const float* __restrict__ bias) {
    int warp = (blockIdx.x * blockDim.x + threadIdx.x) >> 5;
    if (warp >= NN) return;
    int lane = threadIdx.x & 31;
    const float4* hs4 = (const float4*)g_hs;

    int cnt_raw = g_fill[warp];
    float d = rsqrtf((float)(cnt_raw + 1));
    int cnt = (cnt_raw > CAP) ? CAP : cnt_raw;
    const uint16_t* bucket = g_srcidx + (size_t)warp * CAP;

    // reset cursor for the next pipeline run (self-cleaning scratch)
    if (lane == 0) g_fill[warp] = 0;

    float4 acc0 = __ldg(&hs4[(size_t)warp * 32 + lane]);  // self-loop message
    float4 acc1 = make_float4(0.f, 0.f, 0.f, 0.f);

    for (int c = 0; c < cnt; c += 32) {
        int n = min(32, cnt - c);
        int myidx = (c + lane < cnt) ? (int)__ldg(&bucket[c + lane]) : 0;
        int j = 0;
#pragma unroll 2
        for (; j + 1 < n; j += 2) {
            int s0 = __shfl_sync(0xffffffffu, myidx, j);
            int s1 = __shfl_sync(0xffffffffu, myidx, j + 1);
            float4 v0 = __ldg(&hs4[(size_t)s0 * 32 + lane]);
            float4 v1 = __ldg(&hs4[(size_t)s1 * 32 + lane]);
            acc0.x += v0.x; acc0.y += v0.y; acc0.z += v0.z; acc0.w += v0.w;
            acc1.x += v1.x; acc1.y += v1.y; acc1.z += v1.z; acc1.w += v1.w;
        }
        if (j < n) {
            int s = __shfl_sync(0xffffffffu, myidx, j);
            float4 v = __ldg(&hs4[(size_t)s * 32 + lane]);
            acc0.x += v.x; acc0.y += v.y; acc0.z += v.z; acc0.w += v.w;
        }
    }

    float4 b = ((const float4*)bias)[lane];
    float4 o;
    o.x = fmaxf(fmaf(acc0.x + acc1.x, d, b.x), 0.f);
    o.y = fmaxf(fmaf(acc0.y + acc1.y, d, b.y), 0.f);
    o.z = fmaxf(fmaf(acc0.z + acc1.z, d, b.z), 0.f);
    o.w = fmaxf(fmaf(acc0.w + acc1.w, d, b.w), 0.f);
    __stcs(&((float4*)out)[(size_t)warp * 32 + lane], o);
}

// ---------------------------------------------------------------------------
extern "C" void kernel_launch(void* const* d_in, const int* in_sizes, int n_in,
                              void* d_out, int out_size) {
    const float* x    = (const float*)d_in[0];   // [50000,128] f32
    const int*   ei   = (const int*)d_in[1];     // [2,800000] int32
    const float* w    = (const float*)d_in[2];   // [128,128] f32
    const float* bias = (const float*)d_in[3];   // [128] f32
    float* out = (float*)d_out;                  // [50000,128] f32
    (void)in_sizes; (void)n_in; (void)out_size;

    fill_kernel<<<(EE + 255) / 256, 256>>>(ei);
    gemm_kernel<<<(NN + 63) / 64, 256>>>(x, w);
    gather_kernel<<<(NN * 32 + 255) / 256, 256>>>(out, bias);
}

// round 16
// speedup vs baseline: 1.5815x; 1.5815x over previous
#include <cuda_runtime.h>
#include <cstdint>

#define NN 50000
#define EE 800000
#define CC 128
#define CAP 64           // bucket capacity (deg~Poisson(16); P(>64)~2e-18/node)

// Scratch (static __device__ arrays — allocation-free)
__device__ float    g_hs[(size_t)NN * CC];       // hs[j] = (x@W)[j] * dinv[j]
__device__ int      g_fill[NN];                  // per-node cursor == in-degree
__device__ uint16_t g_srcidx[(size_t)NN * CAP];  // padded buckets (u16: NN<65536)

// ---------------------------------------------------------------------------
// 1) zero cursors
__global__ void zero_kernel() {
    int i = blockIdx.x * blockDim.x + threadIdx.x;
    if (i < NN) g_fill[i] = 0;
}

// 2) bucket edges directly (order within bucket irrelevant)
__global__ void fill_kernel(const int* __restrict__ ei) {
    int e = blockIdx.x * blockDim.x + threadIdx.x;
    if (e < EE) {
        int src = ei[e];
        int dst = ei[EE + e];
        int pos = atomicAdd(&g_fill[dst], 1);
        if (pos < CAP)                       // safety guard (never taken)
            g_srcidx[(size_t)dst * CAP + pos] = (uint16_t)src;
    }
}

// ---------------------------------------------------------------------------
// 3) GEMM (fp32 SIMT, at FFMA floor): hs = (x @ W) * dinv[row],
//    dinv inline from fill counters. 256 threads, 64 rows/block;
//    thread = 8 rows x 4 cols. x loaded .cs (read-once, keep L2 for hs).
__global__ void gemm_kernel(const float* __restrict__ x,
                            const float* __restrict__ w) {
    __shared__ float4 sx[64][32];   // 32 KB
    const int row0 = blockIdx.x * 64;
    const int t = threadIdx.x;
    const int lane = t & 31;
    const int wg = t >> 5;          // 8 warps
    const int r0 = wg * 8;

    const float4* x4 = (const float4*)x;
    for (int i = t; i < 64 * 32; i += 256) {
        int r = i >> 5, c = i & 31;
        int row = row0 + r;
        sx[r][c] = (row < NN) ? __ldcs(&x4[(size_t)row * 32 + c])
                              : make_float4(0.f, 0.f, 0.f, 0.f);
    }
    __syncthreads();

    float acc[8][4] = {};
    const float4* w4 = (const float4*)w;

#pragma unroll 2
    for (int k4 = 0; k4 < 32; k4++) {
        float4 wv0 = w4[(k4 * 4 + 0) * 32 + lane];
        float4 wv1 = w4[(k4 * 4 + 1) * 32 + lane];
        float4 wv2 = w4[(k4 * 4 + 2) * 32 + lane];
        float4 wv3 = w4[(k4 * 4 + 3) * 32 + lane];
#pragma unroll
        for (int r = 0; r < 8; r++) {
            float4 xv = sx[r0 + r][k4];  // broadcast, conflict-free
            acc[r][0] += xv.x * wv0.x; acc[r][1] += xv.x * wv0.y;
            acc[r][2] += xv.x * wv0.z; acc[r][3] += xv.x * wv0.w;
            acc[r][0] += xv.y * wv1.x; acc[r][1] += xv.y * wv1.y;
            acc[r][2] += xv.y * wv1.z; acc[r][3] += xv.y * wv1.w;
            acc[r][0] += xv.z * wv2.x; acc[r][1] += xv.z * wv2.y;
            acc[r][2] += xv.z * wv2.z; acc[r][3] += xv.z * wv2.w;
            acc[r][0] += xv.w * wv3.x; acc[r][1] += xv.w * wv3.y;
            acc[r][2] += xv.w * wv3.z; acc[r][3] += xv.w * wv3.w;
        }
    }

    float4* hs4 = (float4*)g_hs;
#pragma unroll
    for (int r = 0; r < 8; r++) {
        int row = row0 + r0 + r;
        if (row < NN) {
            float d = rsqrtf((float)(g_fill[row] + 1));   // dinv inline
            hs4[(size_t)row * 32 + lane] =
                make_float4(acc[r][0] * d, acc[r][1] * d,
                            acc[r][2] * d, acc[r][3] * d);
        }
    }
}

// ---------------------------------------------------------------------------
// 4) Bucket gather (R12 loop, 128-thread blocks for finer load balance):
//    one warp per node; dual accumulators; fused dinv/bias/relu epilogue;
//    streaming store of out (write-once).
__global__ void gather_kernel(float* __restrict__ out,
                              const float* __restrict__ bias) {
    int warp = (blockIdx.x * blockDim.x + threadIdx.x) >> 5;
    if (warp >= NN) return;
    int lane = threadIdx.x & 31;
    const float4* hs4 = (const float4*)g_hs;

    int cnt = g_fill[warp];
    if (cnt > CAP) cnt = CAP;
    const uint16_t* bucket = g_srcidx + (size_t)warp * CAP;

    float4 acc0 = __ldg(&hs4[(size_t)warp * 32 + lane]);  // self-loop message
    float4 acc1 = make_float4(0.f, 0.f, 0.f, 0.f);

    for (int c = 0; c < cnt; c += 32) {
        int n = min(32, cnt - c);
        int myidx = (c + lane < cnt) ? (int)__ldg(&bucket[c + lane]) : 0;
        int j = 0;
#pragma unroll 2
        for (; j + 1 < n; j += 2) {
            int s0 = __shfl_sync(0xffffffffu, myidx, j);
            int s1 = __shfl_sync(0xffffffffu, myidx, j + 1);
            float4 v0 = __ldg(&hs4[(size_t)s0 * 32 + lane]);
            float4 v1 = __ldg(&hs4[(size_t)s1 * 32 + lane]);
            acc0.x += v0.x; acc0.y += v0.y; acc0.z += v0.z; acc0.w += v0.w;
            acc1.x += v1.x; acc1.y += v1.y; acc1.z += v1.z; acc1.w += v1.w;
        }
        if (j < n) {
            int s = __shfl_sync(0xffffffffu, myidx, j);
            float4 v = __ldg(&hs4[(size_t)s * 32 + lane]);
            acc0.x += v.x; acc0.y += v.y; acc0.z += v.z; acc0.w += v.w;
        }
    }

    float d = rsqrtf((float)(g_fill[warp] + 1));
    float4 b = ((const float4*)bias)[lane];
    float4 o;
    o.x = fmaxf(fmaf(acc0.x + acc1.x, d, b.x), 0.f);
    o.y = fmaxf(fmaf(acc0.y + acc1.y, d, b.y), 0.f);
    o.z = fmaxf(fmaf(acc0.z + acc1.z, d, b.z), 0.f);
    o.w = fmaxf(fmaf(acc0.w + acc1.w, d, b.w), 0.f);
    __stcs(&((float4*)out)[(size_t)warp * 32 + lane], o);
}

// ---------------------------------------------------------------------------
extern "C" void kernel_launch(void* const* d_in, const int* in_sizes, int n_in,
                              void* d_out, int out_size) {
    const float* x    = (const float*)d_in[0];   // [50000,128] f32
    const int*   ei   = (const int*)d_in[1];     // [2,800000] int32
    const float* w    = (const float*)d_in[2];   // [128,128] f32
    const float* bias = (const float*)d_in[3];   // [128] f32
    float* out = (float*)d_out;                  // [50000,128] f32
    (void)in_sizes; (void)n_in; (void)out_size;

    zero_kernel<<<(NN + 255) / 256, 256>>>();
    fill_kernel<<<(EE + 255) / 256, 256>>>(ei);
    gemm_kernel<<<(NN + 63) / 64, 256>>>(x, w);
    // 128-thread blocks: 4 warps/CTA -> finer-grained straggler retirement
    gather_kernel<<<(NN * 32 + 127) / 128, 128>>>(out, bias);
}